// round 8
// baseline (speedup 1.0000x reference)
#include <cuda_runtime.h>
#include <cstdint>

#define T_LEN 1024
#define B_SZ  64
#define D_DIM 512
#define N_TAG 24

// Output layout (float32): decoded | pot | lens | trans
#define OFF_POT   (B_SZ * T_LEN)                     // 65536
#define OFF_LENS  (OFF_POT + B_SZ * T_LEN * N_TAG)   // 1638400
#define OFF_TRANS (OFF_LENS + B_SZ)                  // 1638464

typedef unsigned long long u64;

// Packed f32x2 FMA (sm_103a FFMA2 — PTX only)
__device__ __forceinline__ u64 ffma2(u64 a, u64 b, u64 c) {
    u64 d;
    asm("fma.rn.f32x2 %0, %1, %2, %3;" : "=l"(d) : "l"(a), "l"(b), "l"(c));
    return d;
}

struct __align__(16) f4u { u64 lo, hi; };   // one LDS.128 = 2 k-pairs

// ---------------------------------------------------------------------------
// GEMM (proven R5 config, 75us): grid 256 x 128 threads. Block: 256 rows.
// Thread: 4 rows (p+64j) x 12 tags. Per 4-k chunk:
// 12 broadcast W-LDS.128 + 4 x-LDS.128 + 96 FFMA2.
// ---------------------------------------------------------------------------
#define KT     32              // k-floats per x tile
#define NKT    (D_DIM / KT)    // 16
#define XS_STRIDE 18           // u64 per row: 8 float4 data + 1 pad
#define WTAG_F4U (D_DIM / 4)   // f4u per tag row = 128
#define ROWS_BLK 256

extern __shared__ u64 dyn_smem[];

__global__ void __launch_bounds__(128)
gemm_pot_kernel(const float* __restrict__ x,
                const float* __restrict__ W,
                const float* __restrict__ bias,
                const float* __restrict__ lb,
                const float* __restrict__ rb,
                float* __restrict__ potOut) {
    u64* Ws = dyn_smem;                        // [24][256] u64 (tag-major)
    u64* xs = dyn_smem + N_TAG * (D_DIM / 2);  // [256][XS_STRIDE] u64
    float* Wsf = (float*)Ws;

    int tid = threadIdx.x;

    // W transposed into SMEM: Wsf[n*512 + k] = W[k*24 + n] (coalesced LDG)
    for (int i = tid; i < D_DIM * N_TAG; i += 128) {
        int k = i / N_TAG;
        int n = i - k * N_TAG;
        Wsf[n * D_DIM + k] = W[i];
    }

    int p = tid & 63;           // base row id
    int h = tid >> 6;           // tag half: tags [12h, 12h+12)
    int rowg = blockIdx.x * ROWS_BLK;

    const float4* x4g = (const float4*)x + (size_t)rowg * (D_DIM / 4);

    u64 acc[4][12];
#pragma unroll
    for (int j = 0; j < 4; j++)
#pragma unroll
        for (int i = 0; i < 12; i++) acc[j][i] = 0ull;

    const f4u* xrow0 = (const f4u*)(xs + (p)       * XS_STRIDE);
    const f4u* xrow1 = (const f4u*)(xs + (p + 64)  * XS_STRIDE);
    const f4u* xrow2 = (const f4u*)(xs + (p + 128) * XS_STRIDE);
    const f4u* xrow3 = (const f4u*)(xs + (p + 192) * XS_STRIDE);
    const f4u* wb    = (const f4u*)(Ws + (h * 12) * (D_DIM / 2));

    for (int kt = 0; kt < NKT; kt++) {
        __syncthreads();
#pragma unroll
        for (int j = 0; j < 16; j++) {
            int idx = tid + j * 128;          // 0..2047
            int row = idx >> 3;
            int c   = idx & 7;
            float4 v = x4g[(size_t)row * (D_DIM / 4) + kt * 8 + c];
            *(float4*)(xs + row * XS_STRIDE + c * 2) = v;
        }
        __syncthreads();

#pragma unroll
        for (int kk2 = 0; kk2 < KT / 4; kk2++) {
            f4u xv0 = xrow0[kk2];
            f4u xv1 = xrow1[kk2];
            f4u xv2 = xrow2[kk2];
            f4u xv3 = xrow3[kk2];
#pragma unroll
            for (int i = 0; i < 12; i++) {
                f4u wv = wb[i * WTAG_F4U + kt * 8 + kk2];
                acc[0][i] = ffma2(xv0.lo, wv.lo, acc[0][i]);
                acc[0][i] = ffma2(xv0.hi, wv.hi, acc[0][i]);
                acc[1][i] = ffma2(xv1.lo, wv.lo, acc[1][i]);
                acc[1][i] = ffma2(xv1.hi, wv.hi, acc[1][i]);
                acc[2][i] = ffma2(xv2.lo, wv.lo, acc[2][i]);
                acc[2][i] = ffma2(xv2.hi, wv.hi, acc[2][i]);
                acc[3][i] = ffma2(xv3.lo, wv.lo, acc[3][i]);
                acc[3][i] = ffma2(xv3.hi, wv.hi, acc[3][i]);
            }
        }
    }

    float bb[12], lbb[12], rbb[12];
#pragma unroll
    for (int i = 0; i < 12; i++) {
        int n = h * 12 + i;
        bb[i]  = bias[n];
        lbb[i] = lb[n];
        rbb[i] = rb[n];
    }
#pragma unroll
    for (int j = 0; j < 4; j++) {
        int r = rowg + p + j * 64;
        int t = r & (T_LEN - 1);
        float v[12];
#pragma unroll
        for (int i = 0; i < 12; i++) {
            float lo = __uint_as_float((unsigned)(acc[j][i] & 0xffffffffull));
            float hi = __uint_as_float((unsigned)(acc[j][i] >> 32));
            float s = lo + hi + bb[i];
            if (t == 0)         s += lbb[i];
            if (t == T_LEN - 1) s += rbb[i];
            v[i] = s;
        }
        float4* outp = (float4*)(potOut + (size_t)r * N_TAG + h * 12);
        outp[0] = make_float4(v[0], v[1], v[2], v[3]);
        outp[1] = make_float4(v[4], v[5], v[6], v[7]);
        outp[2] = make_float4(v[8], v[9], v[10], v[11]);
    }
}

// ---------------------------------------------------------------------------
// Viterbi, ILP-2: each warp runs TWO independent batch recursions (b, b+32)
// interleaved, overlapping the two latency chains. Alpha broadcast via SMEM
// double-buffer; pot streamed by double-buffered cp.async; backtrace runs
// both batches concurrently in lanes 0/1.
// ---------------------------------------------------------------------------
#define CHUNK 64
#define NCHUNK (T_LEN / CHUNK)          // 16
#define CH_FLOATS (CHUNK * N_TAG)       // 1536 floats = 6144 B
#define CH_BYTES  (CH_FLOATS * 4)
#define BP_STRIDE (31 * 1024 + 992)     // 1023*32 = 32736 per batch

__device__ __forceinline__ void cpasync16(uint32_t s, const void* g) {
    asm volatile("cp.async.cg.shared.global [%0], [%1], 16;" :: "r"(s), "l"(g));
}
__device__ __forceinline__ void cpcommit() {
    asm volatile("cp.async.commit_group;");
}
template <int N> __device__ __forceinline__ void cpwait() {
    asm volatile("cp.async.wait_group %0;" :: "n"(N));
}

extern __shared__ char vit_smem[];   // potS[2][2][1536] f32 | bpA | bpB

__global__ void __launch_bounds__(32, 1)
viterbi_kernel(const float* __restrict__ pot,
               const float* __restrict__ trans,
               float* __restrict__ decodedOut) {
    __shared__ __align__(16) float aBuf[2][2][32];   // [buf][batch][lane]

    float* potS = (float*)vit_smem;                          // 24576 B
    unsigned char* bpA = (unsigned char*)(vit_smem + 4 * CH_BYTES);
    unsigned char* bpB = bpA + BP_STRIDE;

    int b    = blockIdx.x;          // batch A; batch B = b + 32
    int lane = threadIdx.x;
    int ln   = lane < N_TAG ? lane : (N_TAG - 1);

    const float* potA = pot + (size_t)b * T_LEN * N_TAG;
    const float* potB2 = pot + (size_t)(b + 32) * T_LEN * N_TAG;

    float tc[N_TAG];                // shared by both batches (trans is global)
#pragma unroll
    for (int m = 0; m < N_TAG; m++) tc[m] = trans[m * N_TAG + ln];

    uint32_t potS_addr = (uint32_t)__cvta_generic_to_shared(potS);

    // Prologue: chunks 0 and 1 for both batches (one commit group per chunk)
#pragma unroll
    for (int j = 0; j < 12; j++) {
        cpasync16(potS_addr + j * 512 + lane * 16, potA + j * 128 + lane * 4);
        cpasync16(potS_addr + CH_BYTES + j * 512 + lane * 16,
                  potB2 + j * 128 + lane * 4);
    }
    cpcommit();
#pragma unroll
    for (int j = 0; j < 12; j++) {
        cpasync16(potS_addr + 2 * CH_BYTES + j * 512 + lane * 16,
                  potA + CH_FLOATS + j * 128 + lane * 4);
        cpasync16(potS_addr + 3 * CH_BYTES + j * 512 + lane * 16,
                  potB2 + CH_FLOATS + j * 128 + lane * 4);
    }
    cpcommit();
    cpwait<1>();
    __syncwarp();

    float alphaA = potS[ln];                 // t=0 batch A
    float alphaB = potS[CH_FLOATS + ln];     // t=0 batch B
    aBuf[0][0][lane] = alphaA;
    aBuf[0][1][lane] = alphaB;
    __syncwarp();

    for (int c = 0; c < NCHUNK; c++) {
        const float* pcA = potS + (c & 1) * 2 * CH_FLOATS;
        const float* pcB = pcA + CH_FLOATS;
        int tstart = (c == 0) ? 1 : 0;
        for (int tt = tstart; tt < CHUNK; tt++) {
            int t = c * CHUNK + tt;
            int buf = (t - 1) & 1;
            float pcurA = pcA[tt * N_TAG + ln];
            float pcurB = pcB[tt * N_TAG + ln];

            const float4* apA = (const float4*)&aBuf[buf][0][0];
            const float4* apB = (const float4*)&aBuf[buf][1][0];

            float sA[N_TAG], sB[N_TAG];
            int   idxA[N_TAG], idxB[N_TAG];
#pragma unroll
            for (int q = 0; q < 6; q++) {
                float4 va = apA[q];
                float4 vb = apB[q];
                sA[4*q+0] = va.x + tc[4*q+0]; sA[4*q+1] = va.y + tc[4*q+1];
                sA[4*q+2] = va.z + tc[4*q+2]; sA[4*q+3] = va.w + tc[4*q+3];
                sB[4*q+0] = vb.x + tc[4*q+0]; sB[4*q+1] = vb.y + tc[4*q+1];
                sB[4*q+2] = vb.z + tc[4*q+2]; sB[4*q+3] = vb.w + tc[4*q+3];
            }
#pragma unroll
            for (int m = 0; m < N_TAG; m++) { idxA[m] = m; idxB[m] = m; }

            // Contiguous-range tournament (both batches interleaved);
            // strict '>' preserves first-occurrence argmax tie semantics.
#define VCMP2(i, j) { bool gA = sA[j] > sA[i];                     \
                      bool gB = sB[j] > sB[i];                     \
                      idxA[i] = gA ? idxA[j] : idxA[i];            \
                      idxB[i] = gB ? idxB[j] : idxB[i];            \
                      sA[i] = fmaxf(sA[i], sA[j]);                 \
                      sB[i] = fmaxf(sB[i], sB[j]); }
#pragma unroll
            for (int st = 1; st < N_TAG; st <<= 1) {
#pragma unroll
                for (int i = 0; i + st < N_TAG; i += 2 * st) VCMP2(i, i + st)
            }
#undef VCMP2

            alphaA = sA[0] + pcurA;
            alphaB = sB[0] + pcurB;
            aBuf[buf ^ 1][0][lane] = alphaA;
            aBuf[buf ^ 1][1][lane] = alphaB;
            bpA[(t - 1) * 32 + lane] = (unsigned char)idxA[0];
            bpB[(t - 1) * 32 + lane] = (unsigned char)idxB[0];
            __syncwarp();
        }
        // Refill just-consumed buffer with chunk c+2 (both batches)
        if (c + 2 < NCHUNK) {
            uint32_t dst = potS_addr + (c & 1) * 2 * CH_BYTES;
            const float* srcA = potA + (size_t)(c + 2) * CH_FLOATS;
            const float* srcB = potB2 + (size_t)(c + 2) * CH_FLOATS;
#pragma unroll
            for (int j = 0; j < 12; j++) {
                cpasync16(dst + j * 512 + lane * 16, srcA + j * 128 + lane * 4);
                cpasync16(dst + CH_BYTES + j * 512 + lane * 16,
                          srcB + j * 128 + lane * 4);
            }
            cpcommit();
            cpwait<1>();
        } else {
            cpwait<0>();
        }
        __syncwarp();
    }

    // last_tag for both batches (first-occurrence argmax, lanes 0..23)
    float bvA = __shfl_sync(0xffffffffu, alphaA, 0);
    float bvB = __shfl_sync(0xffffffffu, alphaB, 0);
    int btA = 0, btB = 0;
#pragma unroll
    for (int m = 1; m < N_TAG; m++) {
        float vA = __shfl_sync(0xffffffffu, alphaA, m);
        float vB = __shfl_sync(0xffffffffu, alphaB, m);
        if (vA > bvA) { bvA = vA; btA = m; }
        if (vB > bvB) { bvB = vB; btB = m; }
    }

    // Backtrace: lanes 0 and 1 walk the two chains concurrently
    if (lane < 2) {
        const unsigned char* bp = lane ? bpB : bpA;
        float* dec = decodedOut + (size_t)(b + (lane ? 32 : 0)) * T_LEN;
        int tag = lane ? btB : btA;
        dec[T_LEN - 1] = (float)tag;
        for (int t = T_LEN - 2; t >= 0; t--) {
            tag = bp[t * 32 + tag];
            dec[t] = (float)tag;
        }
    }
}

// ---------------------------------------------------------------------------
__global__ void tail_kernel(const float* __restrict__ trans,
                            float* __restrict__ out) {
    int i = threadIdx.x;
    if (i < B_SZ)          out[OFF_LENS + i]  = (float)T_LEN;
    if (i < N_TAG * N_TAG) out[OFF_TRANS + i] = trans[i];
}

// ---------------------------------------------------------------------------
extern "C" void kernel_launch(void* const* d_in, const int* in_sizes, int n_in,
                              void* d_out, int out_size) {
    const float* x     = (const float*)d_in[0];
    const float* W     = (const float*)d_in[1];
    const float* bias  = (const float*)d_in[2];
    const float* trans = (const float*)d_in[3];
    const float* lb    = (const float*)d_in[4];
    const float* rb    = (const float*)d_in[5];

    float* out = (float*)d_out;
    float* pot = out + OFF_POT;

    int gemm_smem = (N_TAG * (D_DIM / 2) + ROWS_BLK * XS_STRIDE) * 8; // 86016
    cudaFuncSetAttribute(gemm_pot_kernel,
                         cudaFuncAttributeMaxDynamicSharedMemorySize, gemm_smem);

    int vit_bytes = 4 * CH_BYTES + 2 * BP_STRIDE;   // 24576 + 65472 = 90048
    cudaFuncSetAttribute(viterbi_kernel,
                         cudaFuncAttributeMaxDynamicSharedMemorySize, vit_bytes);

    gemm_pot_kernel<<<(B_SZ * T_LEN) / ROWS_BLK, 128, gemm_smem>>>(
        x, W, bias, lb, rb, pot);
    tail_kernel<<<1, 640>>>(trans, out);
    viterbi_kernel<<<B_SZ / 2, 32, vit_bytes>>>(pot, trans, out);
}

// round 9
// speedup vs baseline: 2.0457x; 2.0457x over previous
#include <cuda_runtime.h>
#include <cstdint>

#define T_LEN 1024
#define B_SZ  64
#define D_DIM 512
#define N_TAG 24

// Output layout (float32): decoded | pot | lens | trans
#define OFF_POT   (B_SZ * T_LEN)                     // 65536
#define OFF_LENS  (OFF_POT + B_SZ * T_LEN * N_TAG)   // 1638400
#define OFF_TRANS (OFF_LENS + B_SZ)                  // 1638464

typedef unsigned long long u64;

// Packed f32x2 FMA (sm_103a FFMA2 — PTX only)
__device__ __forceinline__ u64 ffma2(u64 a, u64 b, u64 c) {
    u64 d;
    asm("fma.rn.f32x2 %0, %1, %2, %3;" : "=l"(d) : "l"(a), "l"(b), "l"(c));
    return d;
}

struct __align__(16) f4u { u64 lo, hi; };   // one LDS.128 = 2 k-pairs

// ---------------------------------------------------------------------------
// GEMM (proven R5 config): grid 256 x 128 threads. Block: 256 rows.
// Thread: 4 rows (p+64j) x 12 tags. Per 4-k chunk:
// 12 broadcast W-LDS.128 + 4 x-LDS.128 + 96 FFMA2.  DO NOT TOUCH.
// ---------------------------------------------------------------------------
#define KT     32              // k-floats per x tile
#define NKT    (D_DIM / KT)    // 16
#define XS_STRIDE 18           // u64 per row: 8 float4 data + 1 pad
#define WTAG_F4U (D_DIM / 4)   // f4u per tag row = 128
#define ROWS_BLK 256

extern __shared__ u64 dyn_smem[];

__global__ void __launch_bounds__(128)
gemm_pot_kernel(const float* __restrict__ x,
                const float* __restrict__ W,
                const float* __restrict__ bias,
                const float* __restrict__ lb,
                const float* __restrict__ rb,
                float* __restrict__ potOut) {
    u64* Ws = dyn_smem;                        // [24][256] u64 (tag-major)
    u64* xs = dyn_smem + N_TAG * (D_DIM / 2);  // [256][XS_STRIDE] u64
    float* Wsf = (float*)Ws;

    int tid = threadIdx.x;

    // W transposed into SMEM: Wsf[n*512 + k] = W[k*24 + n] (coalesced LDG)
    for (int i = tid; i < D_DIM * N_TAG; i += 128) {
        int k = i / N_TAG;
        int n = i - k * N_TAG;
        Wsf[n * D_DIM + k] = W[i];
    }

    int p = tid & 63;           // base row id
    int h = tid >> 6;           // tag half: tags [12h, 12h+12)
    int rowg = blockIdx.x * ROWS_BLK;

    const float4* x4g = (const float4*)x + (size_t)rowg * (D_DIM / 4);

    u64 acc[4][12];
#pragma unroll
    for (int j = 0; j < 4; j++)
#pragma unroll
        for (int i = 0; i < 12; i++) acc[j][i] = 0ull;

    const f4u* xrow0 = (const f4u*)(xs + (p)       * XS_STRIDE);
    const f4u* xrow1 = (const f4u*)(xs + (p + 64)  * XS_STRIDE);
    const f4u* xrow2 = (const f4u*)(xs + (p + 128) * XS_STRIDE);
    const f4u* xrow3 = (const f4u*)(xs + (p + 192) * XS_STRIDE);
    const f4u* wb    = (const f4u*)(Ws + (h * 12) * (D_DIM / 2));

    for (int kt = 0; kt < NKT; kt++) {
        __syncthreads();
#pragma unroll
        for (int j = 0; j < 16; j++) {
            int idx = tid + j * 128;          // 0..2047
            int row = idx >> 3;
            int c   = idx & 7;
            float4 v = x4g[(size_t)row * (D_DIM / 4) + kt * 8 + c];
            *(float4*)(xs + row * XS_STRIDE + c * 2) = v;
        }
        __syncthreads();

#pragma unroll
        for (int kk2 = 0; kk2 < KT / 4; kk2++) {
            f4u xv0 = xrow0[kk2];
            f4u xv1 = xrow1[kk2];
            f4u xv2 = xrow2[kk2];
            f4u xv3 = xrow3[kk2];
#pragma unroll
            for (int i = 0; i < 12; i++) {
                f4u wv = wb[i * WTAG_F4U + kt * 8 + kk2];
                acc[0][i] = ffma2(xv0.lo, wv.lo, acc[0][i]);
                acc[0][i] = ffma2(xv0.hi, wv.hi, acc[0][i]);
                acc[1][i] = ffma2(xv1.lo, wv.lo, acc[1][i]);
                acc[1][i] = ffma2(xv1.hi, wv.hi, acc[1][i]);
                acc[2][i] = ffma2(xv2.lo, wv.lo, acc[2][i]);
                acc[2][i] = ffma2(xv2.hi, wv.hi, acc[2][i]);
                acc[3][i] = ffma2(xv3.lo, wv.lo, acc[3][i]);
                acc[3][i] = ffma2(xv3.hi, wv.hi, acc[3][i]);
            }
        }
    }

    float bb[12], lbb[12], rbb[12];
#pragma unroll
    for (int i = 0; i < 12; i++) {
        int n = h * 12 + i;
        bb[i]  = bias[n];
        lbb[i] = lb[n];
        rbb[i] = rb[n];
    }
#pragma unroll
    for (int j = 0; j < 4; j++) {
        int r = rowg + p + j * 64;
        int t = r & (T_LEN - 1);
        float v[12];
#pragma unroll
        for (int i = 0; i < 12; i++) {
            float lo = __uint_as_float((unsigned)(acc[j][i] & 0xffffffffull));
            float hi = __uint_as_float((unsigned)(acc[j][i] >> 32));
            float s = lo + hi + bb[i];
            if (t == 0)         s += lbb[i];
            if (t == T_LEN - 1) s += rbb[i];
            v[i] = s;
        }
        float4* outp = (float4*)(potOut + (size_t)r * N_TAG + h * 12);
        outp[0] = make_float4(v[0], v[1], v[2], v[3]);
        outp[1] = make_float4(v[4], v[5], v[6], v[7]);
        outp[2] = make_float4(v[8], v[9], v[10], v[11]);
    }
}

// ---------------------------------------------------------------------------
// Viterbi. One warp per batch (grid 64). pot streamed via double-buffered
// cp.async (proven R5). Alpha broadcast via SMEM double buffer:
// 6 LDS.128 + 2 STS + 1 syncwarp per step instead of 24 SHFLs
// (SHFL single-warp throughput was the R5 bottleneck).
// ---------------------------------------------------------------------------
#define CHUNK 64
#define NCHUNK (T_LEN / CHUNK)          // 16
#define CH_FLOATS (CHUNK * N_TAG)       // 1536 floats = 6144 B

__device__ __forceinline__ void cpasync16(uint32_t s, const void* g) {
    asm volatile("cp.async.cg.shared.global [%0], [%1], 16;" :: "r"(s), "l"(g));
}
__device__ __forceinline__ void cpcommit() {
    asm volatile("cp.async.commit_group;");
}
template <int N> __device__ __forceinline__ void cpwait() {
    asm volatile("cp.async.wait_group %0;" :: "n"(N));
}

__global__ void __launch_bounds__(32, 1)
viterbi_kernel(const float* __restrict__ pot,
               const float* __restrict__ trans,
               float* __restrict__ decodedOut) {
    __shared__ __align__(16) float potS[2][CH_FLOATS];       // 12288 B
    __shared__ __align__(16) float aBuf[2][32];              // 256 B
    __shared__ unsigned char bp_s[(T_LEN - 1) * 32];         // 32736 B

    int b    = blockIdx.x;
    int lane = threadIdx.x;
    int ln   = lane < N_TAG ? lane : (N_TAG - 1);

    const float* potB = pot + (size_t)b * T_LEN * N_TAG;

    float tc[N_TAG];
#pragma unroll
    for (int m = 0; m < N_TAG; m++) tc[m] = trans[m * N_TAG + ln];

    uint32_t potS_addr = (uint32_t)__cvta_generic_to_shared(&potS[0][0]);

    // Issue chunk 0 and chunk 1
#pragma unroll
    for (int j = 0; j < 12; j++)
        cpasync16(potS_addr + j * 512 + lane * 16, potB + j * 128 + lane * 4);
    cpcommit();
#pragma unroll
    for (int j = 0; j < 12; j++)
        cpasync16(potS_addr + 6144 + j * 512 + lane * 16,
                  potB + CH_FLOATS + j * 128 + lane * 4);
    cpcommit();
    cpwait<1>();
    __syncwarp();

    float alpha = potS[0][ln];    // t = 0
    aBuf[0][lane] = alpha;        // slots 24..31 written, never read
    __syncwarp();

    for (int c = 0; c < NCHUNK; c++) {
        const float* pc = potS[c & 1];
        int tstart = (c == 0) ? 1 : 0;
        for (int tt = tstart; tt < CHUNK; tt++) {
            int t = c * CHUNK + tt;
            int buf = (t - 1) & 1;
            float pcur = pc[tt * N_TAG + ln];

            const float4* ap = (const float4*)aBuf[buf];
            float4 a0 = ap[0], a1 = ap[1], a2 = ap[2],
                   a3 = ap[3], a4 = ap[4], a5 = ap[5];

            float s[N_TAG];
            int   idx[N_TAG];
            s[0]  = a0.x + tc[0];  s[1]  = a0.y + tc[1];
            s[2]  = a0.z + tc[2];  s[3]  = a0.w + tc[3];
            s[4]  = a1.x + tc[4];  s[5]  = a1.y + tc[5];
            s[6]  = a1.z + tc[6];  s[7]  = a1.w + tc[7];
            s[8]  = a2.x + tc[8];  s[9]  = a2.y + tc[9];
            s[10] = a2.z + tc[10]; s[11] = a2.w + tc[11];
            s[12] = a3.x + tc[12]; s[13] = a3.y + tc[13];
            s[14] = a3.z + tc[14]; s[15] = a3.w + tc[15];
            s[16] = a4.x + tc[16]; s[17] = a4.y + tc[17];
            s[18] = a4.z + tc[18]; s[19] = a4.w + tc[19];
            s[20] = a5.x + tc[20]; s[21] = a5.y + tc[21];
            s[22] = a5.z + tc[22]; s[23] = a5.w + tc[23];
#pragma unroll
            for (int m = 0; m < N_TAG; m++) idx[m] = m;

            // Contiguous-range tournament; strict '>' preserves
            // first-occurrence argmax tie semantics.
#define VCMP(i, j) { bool g = s[j] > s[i];          \
                     idx[i] = g ? idx[j] : idx[i];   \
                     s[i] = fmaxf(s[i], s[j]); }
#pragma unroll
            for (int st = 1; st < N_TAG; st <<= 1) {
#pragma unroll
                for (int i = 0; i + st < N_TAG; i += 2 * st) VCMP(i, i + st)
            }
#undef VCMP

            alpha = s[0] + pcur;
            aBuf[buf ^ 1][lane] = alpha;
            bp_s[(t - 1) * 32 + lane] = (unsigned char)idx[0];
            __syncwarp();
        }
        // Refill the buffer just consumed with chunk c+2
        if (c + 2 < NCHUNK) {
            uint32_t dst = potS_addr + (c & 1) * 6144;
            const float* src = potB + (size_t)(c + 2) * CH_FLOATS;
#pragma unroll
            for (int j = 0; j < 12; j++)
                cpasync16(dst + j * 512 + lane * 16, src + j * 128 + lane * 4);
            cpcommit();
            cpwait<1>();
        } else {
            cpwait<0>();
        }
        __syncwarp();
    }

    // last_tag = first-occurrence argmax over lanes 0..23
    float bv = __shfl_sync(0xffffffffu, alpha, 0);
    int   bt = 0;
#pragma unroll
    for (int m = 1; m < N_TAG; m++) {
        float v = __shfl_sync(0xffffffffu, alpha, m);
        if (v > bv) { bv = v; bt = m; }
    }

    if (lane == 0) {
        float* dec = decodedOut + (size_t)b * T_LEN;
        int tag = bt;
        dec[T_LEN - 1] = (float)tag;
        for (int t = T_LEN - 2; t >= 0; t--) {
            tag = bp_s[t * 32 + tag];
            dec[t] = (float)tag;
        }
    }
}

// ---------------------------------------------------------------------------
__global__ void tail_kernel(const float* __restrict__ trans,
                            float* __restrict__ out) {
    int i = threadIdx.x;
    if (i < B_SZ)          out[OFF_LENS + i]  = (float)T_LEN;
    if (i < N_TAG * N_TAG) out[OFF_TRANS + i] = trans[i];
}

// ---------------------------------------------------------------------------
extern "C" void kernel_launch(void* const* d_in, const int* in_sizes, int n_in,
                              void* d_out, int out_size) {
    const float* x     = (const float*)d_in[0];
    const float* W     = (const float*)d_in[1];
    const float* bias  = (const float*)d_in[2];
    const float* trans = (const float*)d_in[3];
    const float* lb    = (const float*)d_in[4];
    const float* rb    = (const float*)d_in[5];

    float* out = (float*)d_out;
    float* pot = out + OFF_POT;

    int gemm_smem = (N_TAG * (D_DIM / 2) + ROWS_BLK * XS_STRIDE) * 8; // 86016
    cudaFuncSetAttribute(gemm_pot_kernel,
                         cudaFuncAttributeMaxDynamicSharedMemorySize, gemm_smem);

    gemm_pot_kernel<<<(B_SZ * T_LEN) / ROWS_BLK, 128, gemm_smem>>>(
        x, W, bias, lb, rb, pot);
    tail_kernel<<<1, 640>>>(trans, out);
    viterbi_kernel<<<B_SZ, 32>>>(pot, trans, out);
}

// round 10
// speedup vs baseline: 2.0950x; 1.0241x over previous
#include <cuda_runtime.h>
#include <cstdint>

#define T_LEN 1024
#define B_SZ  64
#define D_DIM 512
#define N_TAG 24

// Output layout (float32): decoded | pot | lens | trans
#define OFF_POT   (B_SZ * T_LEN)                     // 65536
#define OFF_LENS  (OFF_POT + B_SZ * T_LEN * N_TAG)   // 1638400
#define OFF_TRANS (OFF_LENS + B_SZ)                  // 1638464

typedef unsigned long long u64;

// Packed f32x2 ops (sm_103a — PTX only)
__device__ __forceinline__ u64 ffma2(u64 a, u64 b, u64 c) {
    u64 d;
    asm("fma.rn.f32x2 %0, %1, %2, %3;" : "=l"(d) : "l"(a), "l"(b), "l"(c));
    return d;
}
__device__ __forceinline__ u64 fadd2(u64 a, u64 b) {
    u64 d;
    asm("add.rn.f32x2 %0, %1, %2;" : "=l"(d) : "l"(a), "l"(b));
    return d;
}
__device__ __forceinline__ float lof(u64 v) {
    return __uint_as_float((unsigned)(v & 0xffffffffull));
}
__device__ __forceinline__ float hif(u64 v) {
    return __uint_as_float((unsigned)(v >> 32));
}

struct __align__(16) f4u { u64 lo, hi; };   // one LDS.128 = 2 k-pairs

// ---------------------------------------------------------------------------
// GEMM: pot = x @ W + b (+ boundaries).
// 256 threads, 256 rows/block, grid 256. Thread: 4 rows x 6 tags
// (h = tid>>6 keeps W reads warp-uniform/broadcast). acc = 48 u64 regs;
// __launch_bounds__(256,2) caps regs at 128 -> 16 warps/SM.
// Summation order per (row,tag) identical to prior kernel (kt->kk2->lo/hi).
// ---------------------------------------------------------------------------
#define KT     32              // k-floats per x tile
#define NKT    (D_DIM / KT)    // 16
#define XS_STRIDE 18           // u64 per row: 8 float4 data + 1 pad
#define WTAG_F4U (D_DIM / 4)   // f4u per tag row = 128
#define ROWS_BLK 256

extern __shared__ u64 dyn_smem[];

__global__ void __launch_bounds__(256, 2)
gemm_pot_kernel(const float* __restrict__ x,
                const float* __restrict__ W,
                const float* __restrict__ bias,
                const float* __restrict__ lb,
                const float* __restrict__ rb,
                float* __restrict__ potOut) {
    u64* Ws = dyn_smem;                        // [24][256] u64 (tag-major)
    u64* xs = dyn_smem + N_TAG * (D_DIM / 2);  // [256][XS_STRIDE] u64
    float* Wsf = (float*)Ws;

    int tid = threadIdx.x;

    // W transposed into SMEM: Wsf[n*512 + k] = W[k*24 + n] (coalesced LDG)
    for (int i = tid; i < D_DIM * N_TAG; i += 256) {
        int k = i / N_TAG;
        int n = i - k * N_TAG;
        Wsf[n * D_DIM + k] = W[i];
    }

    int rid = tid & 63;         // base row id
    int h   = tid >> 6;         // tag group 0..3: tags [6h, 6h+6)
    int rowg = blockIdx.x * ROWS_BLK;

    const float4* x4g = (const float4*)x + (size_t)rowg * (D_DIM / 4);

    u64 acc[4][6];
#pragma unroll
    for (int j = 0; j < 4; j++)
#pragma unroll
        for (int i = 0; i < 6; i++) acc[j][i] = 0ull;

    const f4u* xrow0 = (const f4u*)(xs + (rid)       * XS_STRIDE);
    const f4u* xrow1 = (const f4u*)(xs + (rid + 64)  * XS_STRIDE);
    const f4u* xrow2 = (const f4u*)(xs + (rid + 128) * XS_STRIDE);
    const f4u* xrow3 = (const f4u*)(xs + (rid + 192) * XS_STRIDE);
    const f4u* wb    = (const f4u*)(Ws + (h * 6) * (D_DIM / 2));

    for (int kt = 0; kt < NKT; kt++) {
        __syncthreads();
        // Stage x tile: 256 rows x 8 float4, fully coalesced (8 per thread)
#pragma unroll
        for (int j = 0; j < 8; j++) {
            int idx = tid + j * 256;          // 0..2047
            int row = idx >> 3;
            int c   = idx & 7;
            float4 v = x4g[(size_t)row * (D_DIM / 4) + kt * 8 + c];
            *(float4*)(xs + row * XS_STRIDE + c * 2) = v;
        }
        __syncthreads();

#pragma unroll
        for (int kk2 = 0; kk2 < KT / 4; kk2++) {
            f4u xv0 = xrow0[kk2];
            f4u xv1 = xrow1[kk2];
            f4u xv2 = xrow2[kk2];
            f4u xv3 = xrow3[kk2];
#pragma unroll
            for (int i = 0; i < 6; i++) {
                f4u wv = wb[i * WTAG_F4U + kt * 8 + kk2];
                acc[0][i] = ffma2(xv0.lo, wv.lo, acc[0][i]);
                acc[0][i] = ffma2(xv0.hi, wv.hi, acc[0][i]);
                acc[1][i] = ffma2(xv1.lo, wv.lo, acc[1][i]);
                acc[1][i] = ffma2(xv1.hi, wv.hi, acc[1][i]);
                acc[2][i] = ffma2(xv2.lo, wv.lo, acc[2][i]);
                acc[2][i] = ffma2(xv2.hi, wv.hi, acc[2][i]);
                acc[3][i] = ffma2(xv3.lo, wv.lo, acc[3][i]);
                acc[3][i] = ffma2(xv3.hi, wv.hi, acc[3][i]);
            }
        }
    }

    float bb[6], lbb[6], rbb[6];
#pragma unroll
    for (int i = 0; i < 6; i++) {
        int n = h * 6 + i;
        bb[i]  = bias[n];
        lbb[i] = lb[n];
        rbb[i] = rb[n];
    }
#pragma unroll
    for (int j = 0; j < 4; j++) {
        int r = rowg + rid + j * 64;
        int t = r & (T_LEN - 1);
        float v[6];
#pragma unroll
        for (int i = 0; i < 6; i++) {
            float s = lof(acc[j][i]) + hif(acc[j][i]) + bb[i];
            if (t == 0)         s += lbb[i];
            if (t == T_LEN - 1) s += rbb[i];
            v[i] = s;
        }
        float2* outp = (float2*)(potOut + (size_t)r * N_TAG + h * 6);
        outp[0] = make_float2(v[0], v[1]);
        outp[1] = make_float2(v[2], v[3]);
        outp[2] = make_float2(v[4], v[5]);
    }
}

// ---------------------------------------------------------------------------
// Viterbi. One warp per batch. pot streamed via double-buffered cp.async;
// alpha broadcast via SMEM double buffer; s = alpha + tc via packed
// add.rn.f32x2 (bitwise == scalar FADD per half).
// ---------------------------------------------------------------------------
#define CHUNK 64
#define NCHUNK (T_LEN / CHUNK)          // 16
#define CH_FLOATS (CHUNK * N_TAG)       // 1536 floats = 6144 B

__device__ __forceinline__ void cpasync16(uint32_t s, const void* g) {
    asm volatile("cp.async.cg.shared.global [%0], [%1], 16;" :: "r"(s), "l"(g));
}
__device__ __forceinline__ void cpcommit() {
    asm volatile("cp.async.commit_group;");
}
template <int N> __device__ __forceinline__ void cpwait() {
    asm volatile("cp.async.wait_group %0;" :: "n"(N));
}

__global__ void __launch_bounds__(32, 1)
viterbi_kernel(const float* __restrict__ pot,
               const float* __restrict__ trans,
               float* __restrict__ decodedOut) {
    __shared__ __align__(16) float potS[2][CH_FLOATS];       // 12288 B
    __shared__ __align__(16) float aBuf[2][32];              // 256 B
    __shared__ unsigned char bp_s[(T_LEN - 1) * 32];         // 32736 B

    int b    = blockIdx.x;
    int lane = threadIdx.x;
    int ln   = lane < N_TAG ? lane : (N_TAG - 1);

    const float* potB = pot + (size_t)b * T_LEN * N_TAG;

    // tc packed in pairs: tc2[j] = (trans[2j][ln], trans[2j+1][ln])
    u64 tc2[12];
#pragma unroll
    for (int j = 0; j < 12; j++) {
        float t0 = trans[(2 * j) * N_TAG + ln];
        float t1 = trans[(2 * j + 1) * N_TAG + ln];
        tc2[j] = (u64)__float_as_uint(t0) | ((u64)__float_as_uint(t1) << 32);
    }

    uint32_t potS_addr = (uint32_t)__cvta_generic_to_shared(&potS[0][0]);

    // Issue chunk 0 and chunk 1
#pragma unroll
    for (int j = 0; j < 12; j++)
        cpasync16(potS_addr + j * 512 + lane * 16, potB + j * 128 + lane * 4);
    cpcommit();
#pragma unroll
    for (int j = 0; j < 12; j++)
        cpasync16(potS_addr + 6144 + j * 512 + lane * 16,
                  potB + CH_FLOATS + j * 128 + lane * 4);
    cpcommit();
    cpwait<1>();
    __syncwarp();

    float alpha = potS[0][ln];    // t = 0
    aBuf[0][lane] = alpha;        // slots 24..31 written, never read
    __syncwarp();

    for (int c = 0; c < NCHUNK; c++) {
        const float* pc = potS[c & 1];
        int tstart = (c == 0) ? 1 : 0;
        for (int tt = tstart; tt < CHUNK; tt++) {
            int t = c * CHUNK + tt;
            int buf = (t - 1) & 1;
            float pcur = pc[tt * N_TAG + ln];

            const f4u* ap = (const f4u*)aBuf[buf];   // 6 x LDS.128 = 24 alphas
            float s[N_TAG];
            int   idx[N_TAG];
#pragma unroll
            for (int q = 0; q < 6; q++) {
                f4u a = ap[q];
                u64 sa = fadd2(a.lo, tc2[2 * q]);
                u64 sb = fadd2(a.hi, tc2[2 * q + 1]);
                s[4 * q + 0] = lof(sa); s[4 * q + 1] = hif(sa);
                s[4 * q + 2] = lof(sb); s[4 * q + 3] = hif(sb);
            }
#pragma unroll
            for (int m = 0; m < N_TAG; m++) idx[m] = m;

            // Contiguous-range tournament; strict '>' preserves
            // first-occurrence argmax tie semantics.
#define VCMP(i, j) { bool g = s[j] > s[i];          \
                     idx[i] = g ? idx[j] : idx[i];   \
                     s[i] = fmaxf(s[i], s[j]); }
#pragma unroll
            for (int st = 1; st < N_TAG; st <<= 1) {
#pragma unroll
                for (int i = 0; i + st < N_TAG; i += 2 * st) VCMP(i, i + st)
            }
#undef VCMP

            alpha = s[0] + pcur;
            aBuf[buf ^ 1][lane] = alpha;
            bp_s[(t - 1) * 32 + lane] = (unsigned char)idx[0];
            __syncwarp();
        }
        // Refill the buffer just consumed with chunk c+2
        if (c + 2 < NCHUNK) {
            uint32_t dst = potS_addr + (c & 1) * 6144;
            const float* src = potB + (size_t)(c + 2) * CH_FLOATS;
#pragma unroll
            for (int j = 0; j < 12; j++)
                cpasync16(dst + j * 512 + lane * 16, src + j * 128 + lane * 4);
            cpcommit();
            cpwait<1>();
        } else {
            cpwait<0>();
        }
        __syncwarp();
    }

    // last_tag = first-occurrence argmax over lanes 0..23
    float bv = __shfl_sync(0xffffffffu, alpha, 0);
    int   bt = 0;
#pragma unroll
    for (int m = 1; m < N_TAG; m++) {
        float v = __shfl_sync(0xffffffffu, alpha, m);
        if (v > bv) { bv = v; bt = m; }
    }

    if (lane == 0) {
        float* dec = decodedOut + (size_t)b * T_LEN;
        int tag = bt;
        dec[T_LEN - 1] = (float)tag;
        for (int t = T_LEN - 2; t >= 0; t--) {
            tag = bp_s[t * 32 + tag];
            dec[t] = (float)tag;
        }
    }
}

// ---------------------------------------------------------------------------
__global__ void tail_kernel(const float* __restrict__ trans,
                            float* __restrict__ out) {
    int i = threadIdx.x;
    if (i < B_SZ)          out[OFF_LENS + i]  = (float)T_LEN;
    if (i < N_TAG * N_TAG) out[OFF_TRANS + i] = trans[i];
}

// ---------------------------------------------------------------------------
extern "C" void kernel_launch(void* const* d_in, const int* in_sizes, int n_in,
                              void* d_out, int out_size) {
    const float* x     = (const float*)d_in[0];
    const float* W     = (const float*)d_in[1];
    const float* bias  = (const float*)d_in[2];
    const float* trans = (const float*)d_in[3];
    const float* lb    = (const float*)d_in[4];
    const float* rb    = (const float*)d_in[5];

    float* out = (float*)d_out;
    float* pot = out + OFF_POT;

    int gemm_smem = (N_TAG * (D_DIM / 2) + ROWS_BLK * XS_STRIDE) * 8; // 85- KB
    cudaFuncSetAttribute(gemm_pot_kernel,
                         cudaFuncAttributeMaxDynamicSharedMemorySize, gemm_smem);

    gemm_pot_kernel<<<(B_SZ * T_LEN) / ROWS_BLK, 256, gemm_smem>>>(
        x, W, bias, lb, rb, pot);
    tail_kernel<<<1, 640>>>(trans, out);
    viterbi_kernel<<<B_SZ, 32>>>(pot, trans, out);
}